// round 1
// baseline (speedup 1.0000x reference)
#include <cuda_runtime.h>

// Problem constants
#define HW     262144        // 512*512
#define NB_B   2
#define NCH    48
#define NC3    144
#define NHEADS 8

// Scratch (device globals: no allocation allowed)
__device__ float g_qkv[NB_B * NC3 * HW];     // after 1x1 qkv conv
__device__ float g_dw[NB_B * NC3 * HW];      // after depthwise 3x3
__device__ float g_ao[NB_B * NCH * HW];      // after attn@V (from_blocks layout)
__device__ float g_norm2[NB_B * 96 * 16];    // per (b, q/k-channel, y%4, x%4) sum of squares
__device__ float g_S[NB_B * NHEADS * 96 * 96]; // gram -> softmaxed attn

typedef unsigned long long u64;

__device__ __forceinline__ void fma2(u64& d, u64 a, u64 b) {
    asm("fma.rn.f32x2 %0, %1, %2, %0;" : "+l"(d) : "l"(a), "l"(b));
}
__device__ __forceinline__ u64 pk2(float lo, float hi) {
    u64 r; asm("mov.b64 %0, {%1, %2};" : "=l"(r) : "f"(lo), "f"(hi)); return r;
}
__device__ __forceinline__ float hsum(u64 v) {
    float lo, hi; asm("mov.b64 {%0, %1}, %2;" : "=f"(lo), "=f"(hi) : "l"(v)); return lo + hi;
}
__device__ __forceinline__ void up2(u64 v, float& lo, float& hi) {
    asm("mov.b64 {%0, %1}, %2;" : "=f"(lo), "=f"(hi) : "l"(v));
}

// ---------------------------------------------------------------------------
// K0: zero the accumulation buffers
// ---------------------------------------------------------------------------
__global__ void k_zero() {
    int i = blockIdx.x * 256 + threadIdx.x;
    if (i < NB_B * NHEADS * 96 * 96) g_S[i] = 0.f;
    if (i < NB_B * 96 * 16)          g_norm2[i] = 0.f;
}

// ---------------------------------------------------------------------------
// K1: 1x1 conv 48 -> 144 (per-pixel GEMV, f32x2 over ic pairs)
// ---------------------------------------------------------------------------
__global__ void __launch_bounds__(256) k_qkv(const float* __restrict__ x,
                                             const float* __restrict__ w) {
    __shared__ __align__(16) float ws[NC3 * NCH];
    int tid = threadIdx.x;
    for (int e = tid; e < NC3 * NCH; e += 256) ws[e] = w[e];
    __syncthreads();

    int p = blockIdx.x * 256 + tid;          // global pixel over B*HW
    int b = p >> 18;
    int q = p & (HW - 1);
    const float* xb = x + b * (NCH * HW) + q;

    u64 xp[24];
#pragma unroll
    for (int j = 0; j < 24; j++) {
        float a = xb[(2 * j) * HW];
        float c = xb[(2 * j + 1) * HW];
        xp[j] = pk2(a, c);
    }

    float* op = g_qkv + b * (NC3 * HW) + q;
    const ulonglong2* w2 = (const ulonglong2*)ws;
    for (int oc = 0; oc < NC3; oc++) {
        const ulonglong2* wr = w2 + oc * 12;
        u64 a0 = 0, a1 = 0, a2 = 0, a3 = 0;
#pragma unroll
        for (int j = 0; j < 12; j += 2) {
            ulonglong2 wa = wr[j];
            ulonglong2 wb = wr[j + 1];
            fma2(a0, wa.x, xp[2 * j + 0]);
            fma2(a1, wa.y, xp[2 * j + 1]);
            fma2(a2, wb.x, xp[2 * j + 2]);
            fma2(a3, wb.y, xp[2 * j + 3]);
        }
        op[oc * HW] = hsum(a0) + hsum(a1) + hsum(a2) + hsum(a3);
    }
}

// ---------------------------------------------------------------------------
// K2: depthwise 3x3 (zero pad) + fused q/k squared-norm accumulation
// blockDim (16,8); each thread computes 4 consecutive x outputs
// ---------------------------------------------------------------------------
__global__ void __launch_bounds__(128) k_dw(const float* __restrict__ dww) {
    int ch = blockIdx.z % NC3;
    int b  = blockIdx.z / NC3;
    __shared__ float wk[9];
    __shared__ float sb[16];
    int tid = threadIdx.y * 16 + threadIdx.x;
    if (tid < 9)  wk[tid] = dww[ch * 9 + tid];
    if (tid < 16) sb[tid] = 0.f;
    __syncthreads();

    int x0 = (blockIdx.x * 16 + threadIdx.x) * 4;
    int y0 = blockIdx.y * 8 + threadIdx.y;
    const float* in = g_qkv + (b * NC3 + ch) * HW;

    float v[3][6];
#pragma unroll
    for (int r = 0; r < 3; r++) {
        int y = y0 + r - 1;
        if (y >= 0 && y < 512) {
            const float* rp = in + y * 512;
            float4 m = *(const float4*)(rp + x0);
            v[r][0] = (x0 > 0) ? rp[x0 - 1] : 0.f;
            v[r][1] = m.x; v[r][2] = m.y; v[r][3] = m.z; v[r][4] = m.w;
            v[r][5] = (x0 + 4 < 512) ? rp[x0 + 4] : 0.f;
        } else {
#pragma unroll
            for (int c = 0; c < 6; c++) v[r][c] = 0.f;
        }
    }

    float o[4];
#pragma unroll
    for (int px = 0; px < 4; px++) {
        float s = 0.f;
#pragma unroll
        for (int r = 0; r < 3; r++)
#pragma unroll
            for (int c = 0; c < 3; c++)
                s += wk[r * 3 + c] * v[r][px + c];
        o[px] = s;
    }
    float4 ov = make_float4(o[0], o[1], o[2], o[3]);
    *(float4*)(g_dw + (b * NC3 + ch) * HW + y0 * 512 + x0) = ov;

    if (ch < 96) {  // q and k channels feed the L2-norm buckets
#pragma unroll
        for (int px = 0; px < 4; px++) {
            float s = o[px] * o[px];
            s += __shfl_xor_sync(0xffffffffu, s, 8);
            s += __shfl_xor_sync(0xffffffffu, s, 4);
            s += __shfl_xor_sync(0xffffffffu, s, 2);
            s += __shfl_xor_sync(0xffffffffu, s, 1);
            if ((tid & 15) == 0) atomicAdd(&sb[(y0 & 3) * 4 + px], s);
        }
        __syncthreads();
        if (tid < 16) atomicAdd(&g_norm2[(b * 96 + ch) * 16 + tid], sb[tid]);
    }
}

// ---------------------------------------------------------------------------
// K3: raw gram  S[b,h,r,d] = sum_n q_r[n] * k_d[n]  over n = 16384 block-cols
// grid (32 col-chunks x 16 bh); block 256 thr, 6x6 register tile, f32x2 k-pairs
// ---------------------------------------------------------------------------
__global__ void __launch_bounds__(256) k_gram() {
    int bh = blockIdx.y;
    int b = bh >> 3, h = bh & 7;
    int chunk = blockIdx.x;                  // 512 columns per chunk
    __shared__ __align__(16) float qs[96 * 18];
    __shared__ __align__(16) float ks[96 * 18];
    int tid = threadIdx.x;
    int ty = tid >> 4, tx = tid & 15;
    int kk = tid & 15;

    const float* qb = g_dw + (b * NC3 + h * 6) * HW;
    const float* kb = qb + 48 * HW;

    int offs[6];
#pragma unroll
    for (int u = 0; u < 6; u++) {
        int row = u * 16 + ty;
        int cc = row >> 4, nh = (row >> 2) & 3, nw = row & 3;
        offs[u] = cc * HW + nh * 512 + nw + 4 * kk;
    }

    u64 A[36];
#pragma unroll
    for (int e = 0; e < 36; e++) A[e] = 0;

    for (int step = 0; step < 32; step++) {
        int so = (chunk * 4 + (step >> 3)) * (4 * 512) + (step & 7) * 64;
#pragma unroll
        for (int u = 0; u < 6; u++) {
            int sidx = (u * 16 + ty) * 18 + kk;
            qs[sidx] = qb[offs[u] + so];
            ks[sidx] = kb[offs[u] + so];
        }
        __syncthreads();
#pragma unroll
        for (int k2 = 0; k2 < 8; k2++) {
            u64 qv[6], kv[6];
#pragma unroll
            for (int a = 0; a < 6; a++)
                qv[a] = *(const u64*)&qs[(6 * ty + a) * 18 + 2 * k2];
#pragma unroll
            for (int d = 0; d < 6; d++)
                kv[d] = *(const u64*)&ks[(6 * tx + d) * 18 + 2 * k2];
#pragma unroll
            for (int a = 0; a < 6; a++)
#pragma unroll
                for (int d = 0; d < 6; d++)
                    fma2(A[a * 6 + d], qv[a], kv[d]);
        }
        __syncthreads();
    }

    float* Sp = g_S + bh * (96 * 96);
#pragma unroll
    for (int a = 0; a < 6; a++)
#pragma unroll
        for (int d = 0; d < 6; d++)
            atomicAdd(&Sp[(6 * ty + a) * 96 + (6 * tx + d)], hsum(A[a * 6 + d]));
}

// ---------------------------------------------------------------------------
// K4: fold norms + temperature, softmax rows (in-place in g_S)
// ---------------------------------------------------------------------------
__global__ void k_soft(const float* __restrict__ temp) {
    int bh = blockIdx.x;
    int b = bh >> 3, h = bh & 7;
    int r = threadIdx.x;                     // 0..95
    __shared__ float nk[96];

    float sq = g_norm2[(b * 96 + h * 6 + (r >> 4)) * 16 + (r & 15)];
    float nq = fmaxf(sqrtf(sq), 1e-12f);
    float sk = g_norm2[(b * 96 + 48 + h * 6 + (r >> 4)) * 16 + (r & 15)];
    nk[r] = fmaxf(sqrtf(sk), 1e-12f);
    __syncthreads();

    float t = temp[h];
    float* row = g_S + (bh * 96 + r) * 96;
    float vals[96];
    float m = -1e30f;
#pragma unroll
    for (int d = 0; d < 96; d++) {
        float a = row[d] / (nq * nk[d]) * t;
        vals[d] = a;
        m = fmaxf(m, a);
    }
    float ssum = 0.f;
#pragma unroll
    for (int d = 0; d < 96; d++) {
        float e = expf(vals[d] - m);
        vals[d] = e;
        ssum += e;
    }
    float inv = 1.f / ssum;
#pragma unroll
    for (int d = 0; d < 96; d++) row[d] = vals[d] * inv;
}

// ---------------------------------------------------------------------------
// K5: out = attn @ v, written directly in from_blocks (NCHW) layout
// grid (256 col-tiles x 16 bh); block 256 thr; 6 rows x 4 cols per thread
// dyn smem: atT[96][97] (attn transposed) + vs[96][64]
// ---------------------------------------------------------------------------
extern __shared__ float dynsm[];
__global__ void __launch_bounds__(256) k_av() {
    int bh = blockIdx.y;
    int b = bh >> 3, h = bh & 7;
    int tid = threadIdx.x;
    int ty = tid >> 4, tx = tid & 15;

    float* atT = dynsm;                  // 96*97 floats
    float* vs  = dynsm + 96 * 97;        // 96*64 floats

    const float* Sp = g_S + bh * 9216;
    for (int e = tid; e < 9216; e += 256) {
        int r = e / 96;
        int d = e - r * 96;
        atT[d * 97 + r] = Sp[e];
    }

    int n0 = blockIdx.x * 64;
    int i  = n0 >> 7;
    int j0 = n0 & 127;
    const float* vb = g_dw + (b * NC3 + 96 + h * 6) * HW;
    for (int e = tid; e < 6144; e += 256) {
        int d = e >> 6, c = e & 63;
        int dc = d >> 4, dh = (d >> 2) & 3, dwv = d & 3;
        vs[d * 64 + c] = vb[dc * HW + (4 * i + dh) * 512 + 4 * (j0 + c) + dwv];
    }
    __syncthreads();

    u64 A[12];
#pragma unroll
    for (int e = 0; e < 12; e++) A[e] = 0;

#pragma unroll 4
    for (int kd = 0; kd < 96; kd++) {
        float a[6];
#pragma unroll
        for (int u = 0; u < 6; u++) a[u] = atT[kd * 97 + 6 * ty + u];
        ulonglong2 v2 = *(const ulonglong2*)&vs[kd * 64 + 4 * tx];
#pragma unroll
        for (int u = 0; u < 6; u++) {
            u64 asp = pk2(a[u], a[u]);
            fma2(A[u * 2 + 0], asp, v2.x);
            fma2(A[u * 2 + 1], asp, v2.y);
        }
    }

    float* ob = g_ao + (b * NCH + h * 6) * HW;
#pragma unroll
    for (int u = 0; u < 6; u++) {
        int r = 6 * ty + u;
        int cc = r >> 4, nh = (r >> 2) & 3, nw = r & 3;
        int base = cc * HW + (4 * i + nh) * 512 + nw;
        float c0, c1, c2, c3;
        up2(A[u * 2 + 0], c0, c1);
        up2(A[u * 2 + 1], c2, c3);
        int j = j0 + 4 * tx;
        ob[base + 4 * (j + 0)] = c0;
        ob[base + 4 * (j + 1)] = c1;
        ob[base + 4 * (j + 2)] = c2;
        ob[base + 4 * (j + 3)] = c3;
    }
}

// ---------------------------------------------------------------------------
// K6: 1x1 proj 48 -> 48 into d_out
// ---------------------------------------------------------------------------
__global__ void __launch_bounds__(256) k_proj(const float* __restrict__ w,
                                              float* __restrict__ out) {
    __shared__ __align__(16) float ws[NCH * NCH];
    int tid = threadIdx.x;
    for (int e = tid; e < NCH * NCH; e += 256) ws[e] = w[e];
    __syncthreads();

    int p = blockIdx.x * 256 + tid;
    int b = p >> 18;
    int q = p & (HW - 1);
    const float* xb = g_ao + b * (NCH * HW) + q;

    u64 xp[24];
#pragma unroll
    for (int j = 0; j < 24; j++) {
        float a = xb[(2 * j) * HW];
        float c = xb[(2 * j + 1) * HW];
        xp[j] = pk2(a, c);
    }

    float* op = out + b * (NCH * HW) + q;
    const ulonglong2* w2 = (const ulonglong2*)ws;
    for (int oc = 0; oc < NCH; oc++) {
        const ulonglong2* wr = w2 + oc * 12;
        u64 a0 = 0, a1 = 0, a2 = 0, a3 = 0;
#pragma unroll
        for (int j = 0; j < 12; j += 2) {
            ulonglong2 wa = wr[j];
            ulonglong2 wb = wr[j + 1];
            fma2(a0, wa.x, xp[2 * j + 0]);
            fma2(a1, wa.y, xp[2 * j + 1]);
            fma2(a2, wb.x, xp[2 * j + 2]);
            fma2(a3, wb.y, xp[2 * j + 3]);
        }
        op[oc * HW] = hsum(a0) + hsum(a1) + hsum(a2) + hsum(a3);
    }
}

// ---------------------------------------------------------------------------
extern "C" void kernel_launch(void* const* d_in, const int* in_sizes, int n_in,
                              void* d_out, int out_size) {
    const float* x     = (const float*)d_in[0];
    const float* qkvw  = (const float*)d_in[1];
    const float* dww   = (const float*)d_in[2];
    const float* projw = (const float*)d_in[3];
    const float* temp  = (const float*)d_in[4];
    float* out = (float*)d_out;

    static int smem_set = 0;
    // idempotent, host-side attribute (not a stream op; safe under capture)
    cudaFuncSetAttribute(k_av, cudaFuncAttributeMaxDynamicSharedMemorySize,
                         (96 * 97 + 96 * 64) * 4);
    (void)smem_set;

    k_zero<<<576, 256>>>();
    k_qkv<<<2048, 256>>>(x, qkvw);
    k_dw<<<dim3(8, 64, NB_B * NC3), dim3(16, 8)>>>(dww);
    k_gram<<<dim3(32, NB_B * NHEADS), 256>>>();
    k_soft<<<NB_B * NHEADS, 96>>>(temp);
    k_av<<<dim3(256, NB_B * NHEADS), 256, (96 * 97 + 96 * 64) * 4>>>();
    k_proj<<<2048, 256>>>(projw, out);
}